// round 17
// baseline (speedup 1.0000x reference)
#include <cuda_runtime.h>
#include <cuda_bf16.h>
#include <math.h>
#include <stdint.h>

#define T  2048
#define C  1024
#define NH 16
#define HD 64
#define KD 8
#define EPSV 1e-6f
#define NEGV -1000000000.0f
#define GRID_F 148

// ---------------- scratch (static device globals; no allocation) ----------------
__device__ float g_qd[T * KD];
__device__ float g_kd[T * KD];
__device__ unsigned int g_mask32[(size_t)T * 64];   // bit-packed mask [T][64] uint32
__device__ int g_need;
__device__ unsigned char g_any[T];

__device__ volatile int g_bar_count;
__device__ volatile int g_bar_gen;

__device__ float g_xpart[GRID_F * C];
__device__ float g_xsum[C];
__device__ float g_vpart[32 * C];
__device__ float g_opart[32 * C];

__device__ __nv_bfloat16 g_xcat[T * 3 * C];    // [2048][3072]  hi | lo | hi
__device__ __nv_bfloat16 g_ycat[T * 3 * C];
__device__ __nv_bfloat16 g_Wqt[C * C];
__device__ __nv_bfloat16 g_Wkt[C * C];
__device__ __nv_bfloat16 g_Wvt[C * 3 * C];     // [N][3K]  hi | hi | lo
__device__ __nv_bfloat16 g_Wpt[C * 3 * C];
__device__ __nv_bfloat16 g_Qraw[T * C];
__device__ __nv_bfloat16 g_Kraw[T * C];
__device__ __nv_bfloat16 g_Qb[T * C];
__device__ __nv_bfloat16 g_Kb[T * C];
__device__ __nv_bfloat16 g_Vhi[T * C];
__device__ __nv_bfloat16 g_Vlo[T * C];

// ================= helpers =================
__device__ __forceinline__ uint32_t smem_u32(const void* p) {
    return (uint32_t)__cvta_generic_to_shared(p);
}
#define SMEM_SWIZZLE_128B(byte_offset) ((byte_offset) ^ (((byte_offset) >> 3) & 0x70))

__device__ __forceinline__ void ldmatrix_x4(uint32_t* r, uint32_t addr) {
    asm volatile("ldmatrix.sync.aligned.m8n8.x4.shared.b16 {%0,%1,%2,%3}, [%4];"
                 : "=r"(r[0]), "=r"(r[1]), "=r"(r[2]), "=r"(r[3]) : "r"(addr));
}
__device__ __forceinline__ void ldmatrix_x2_trans(uint32_t* r, uint32_t addr) {
    asm volatile("ldmatrix.sync.aligned.m8n8.x2.trans.shared.b16 {%0,%1}, [%2];"
                 : "=r"(r[0]), "=r"(r[1]) : "r"(addr));
}
__device__ __forceinline__ void mma_bf16(float* d, const uint32_t* a, const uint32_t* b) {
    asm volatile("mma.sync.aligned.m16n8k16.row.col.f32.bf16.bf16.f32 "
                 "{%0,%1,%2,%3},{%4,%5,%6,%7},{%8,%9},{%0,%1,%2,%3};"
                 : "+f"(d[0]), "+f"(d[1]), "+f"(d[2]), "+f"(d[3])
                 : "r"(a[0]), "r"(a[1]), "r"(a[2]), "r"(a[3]), "r"(b[0]), "r"(b[1]));
}
__device__ __forceinline__ void cp_async16(uint32_t dst, const void* src) {
    asm volatile("cp.async.cg.shared.global [%0], [%1], 16;" :: "r"(dst), "l"(src));
}
__device__ __forceinline__ uint32_t pack_bf16(float lo, float hi) {
    uint32_t r;
    asm("cvt.rn.bf16x2.f32 %0, %1, %2;" : "=r"(r) : "f"(hi), "f"(lo));
    return r;
}
__device__ __forceinline__ float fast_exp(float x) {
    float a = fmaxf(x * 1.4426950408889634f, -126.0f);
    float ai = floorf(a);
    float f = a - ai;
    float p = 1.525273e-5f;
    p = fmaf(p, f, 1.5403530e-4f);
    p = fmaf(p, f, 1.3333558e-3f);
    p = fmaf(p, f, 9.6181291e-3f);
    p = fmaf(p, f, 5.5504109e-2f);
    p = fmaf(p, f, 2.4022651e-1f);
    p = fmaf(p, f, 6.9314718e-1f);
    p = fmaf(p, f, 1.0f);
    int ei = (int)ai;
    return p * __uint_as_float((uint32_t)(ei + 127) << 23);
}

// generation-counter grid barrier; safe: grid == GRID_F <= SM count => co-resident
__device__ __forceinline__ void grid_sync() {
    __syncthreads();
    if (threadIdx.x == 0) {
        __threadfence();
        int gen = g_bar_gen;
        if (atomicAdd((int*)&g_bar_count, 1) == GRID_F - 1) {
            g_bar_count = 0;
            __threadfence();
            g_bar_gen = gen + 1;
        } else {
            while (g_bar_gen == gen) { }
        }
        __threadfence();
    }
    __syncthreads();
}

// ================= fused always-path kernel =================
__global__ __launch_bounds__(256) void fused_light_kernel(
    const float* __restrict__ x,
    const float* __restrict__ Wdq, const float* __restrict__ Wdk,
    const float* __restrict__ Wv,  const float* __restrict__ Wp,
    float* __restrict__ out)
{
    __shared__ float sred[C];
    const int tid = threadIdx.x, wid = tid >> 5, lane = tid & 31;
    const int b = blockIdx.x;

    if (b == 0 && tid == 0) g_need = 0;

    // ---- P1a: qd/kd (warp per row) ----
    for (int r = b * 8 + wid; r < T; r += GRID_F * 8) {
        float aq[KD], ak[KD];
#pragma unroll
        for (int j = 0; j < KD; j++) { aq[j] = 0.0f; ak[j] = 0.0f; }
        for (int k = lane; k < C; k += 32) {
            float xv = x[(size_t)r * C + k];
#pragma unroll
            for (int j = 0; j < KD; j++) {
                aq[j] += xv * Wdq[k * KD + j];
                ak[j] += xv * Wdk[k * KD + j];
            }
        }
#pragma unroll
        for (int j = 0; j < KD; j++) {
#pragma unroll
            for (int off = 16; off; off >>= 1) {
                aq[j] += __shfl_xor_sync(0xffffffffu, aq[j], off);
                ak[j] += __shfl_xor_sync(0xffffffffu, ak[j], off);
            }
        }
        if (lane == 0) {
#pragma unroll
            for (int j = 0; j < KD; j++) {
                g_qd[r * KD + j] = aq[j];
                g_kd[r * KD + j] = ak[j];
            }
        }
    }
    // ---- P1b: x column partial sums (up to 14 rows per block) ----
    {
        int r0 = b * 14;
        int r1 = min(T, r0 + 14);
        for (int c = tid; c < C; c += 256) {
            float a = 0.0f;
            for (int r = r0; r < r1; r++) a += x[(size_t)r * C + c];
            g_xpart[b * C + c] = a;
        }
    }
    grid_sync();

    // ---- P2a: ballot mask (tasks 0..127, 16 q rows each) ----
    if (b < 128) {
        int qA = b * 16 + wid * 2;
        int qB = qA + 1;
        float4 qa0 = *(const float4*)&g_qd[qA * KD];
        float4 qb0 = *(const float4*)&g_qd[qA * KD + 4];
        float4 qa1 = *(const float4*)&g_qd[qB * KD];
        float4 qb1 = *(const float4*)&g_qd[qB * KD + 4];
        unsigned accA = 0, accB = 0;
        for (int kc = 0; kc < 64; kc++) {
            int k = kc * 32 + lane;
            float4 ka = *(const float4*)&g_kd[k * KD];
            float4 kb = *(const float4*)&g_kd[k * KD + 4];
            bool mA = (k <= qA)
                && (qa0.x == ka.x) && (qa0.y == ka.y) && (qa0.z == ka.z) && (qa0.w == ka.w)
                && (qb0.x == kb.x) && (qb0.y == kb.y) && (qb0.z == kb.z);
            bool mB = (k <= qB)
                && (qa1.x == ka.x) && (qa1.y == ka.y) && (qa1.z == ka.z) && (qa1.w == ka.w)
                && (qb1.x == kb.x) && (qb1.y == kb.y) && (qb1.z == kb.z);
            unsigned bA = __ballot_sync(0xffffffffu, mA);
            unsigned bB = __ballot_sync(0xffffffffu, mB);
            if (lane == 0) {
                g_mask32[(size_t)qA * 64 + kc] = bA;
                g_mask32[(size_t)qB * 64 + kc] = bB;
            }
            accA |= bA;
            accB |= bB;
        }
        if (lane == 0) {
            g_any[qA] = accA ? 1 : 0;
            g_any[qB] = accB ? 1 : 0;
            int add = (accA ? 1 : 0) + (accB ? 1 : 0);
            if (add) atomicAdd(&g_need, add);
        }
    }
    // ---- P2b: xsum final reduce (blocks 128..131) ----
    else if (b < 132) {
        int c = (b - 128) * 256 + tid;
        float a = 0.0f;
        for (int p = 0; p < GRID_F; p++) a += g_xpart[p * C + c];
        g_xsum[c] = a;
    }
    grid_sync();

    // ---- P3: vbar partials (tasks 0..127: 32 k-chunks x 4 n-slices) ----
    if (b < 128) {
        int kc = b >> 2;
        int n  = (b & 3) * 256 + tid;
        int k0 = kc * 32;
        if (tid < 32) sred[tid] = g_xsum[k0 + tid];
        __syncthreads();
        float a = 0.0f;
#pragma unroll
        for (int k = 0; k < 32; k++) a += sred[k] * Wv[(size_t)(k0 + k) * C + n];
        g_vpart[kc * C + n] = a;
    }
    grid_sync();

    // ---- P4: obar partials ----
    if (b < 128) {
        int kc = b >> 2;
        int n  = (b & 3) * 256 + tid;
        int k0 = kc * 32;
        if (tid < 32) {
            float a = 0.0f;
#pragma unroll
            for (int p = 0; p < 32; p++) a += g_vpart[p * C + k0 + tid];
            sred[tid] = a * (1.0f / 2048.0f);
        }
        __syncthreads();
        float a = 0.0f;
#pragma unroll
        for (int k = 0; k < 32; k++) a += sred[k] * Wp[(size_t)(k0 + k) * C + n];
        g_opart[kc * C + n] = a;
    }
    grid_sync();

    // ---- P5: per-block obar reduce + broadcast to generic rows ----
    for (int c = tid; c < C; c += 256) {
        float a = 0.0f;
#pragma unroll
        for (int p = 0; p < 32; p++) a += g_opart[p * C + c];
        sred[c] = a;
    }
    __syncthreads();
    {
        int r0 = b * 14;
        int r1 = min(T, r0 + 14);
        for (int r = r0; r < r1; r++) {
            if (g_any[r]) continue;
            float4* o = (float4*)(out + (size_t)r * C);
            for (int c4 = tid; c4 < C / 4; c4 += 256) o[c4] = ((const float4*)sred)[c4];
        }
    }
}

// ================= gated heavy-path kernels =================
// prep: z<4 -> weight transpose/convert; z==4 -> x hi/lo/hi split
__global__ __launch_bounds__(256) void prep_kernel(
    const float* __restrict__ x,
    const float* __restrict__ Wq, const float* __restrict__ Wk,
    const float* __restrict__ Wv, const float* __restrict__ Wp)
{
    if (g_need == 0) return;
    __shared__ float tile[32][33];
    int z = blockIdx.z;
    if (z == 4) {
        int bid = blockIdx.y * 32 + blockIdx.x;
#pragma unroll
        for (int rr = 0; rr < 2; rr++) {
            int r = bid * 2 + rr;
            for (int c = threadIdx.x; c < C; c += 256) {
                float v = x[(size_t)r * C + c];
                __nv_bfloat16 hi = __float2bfloat16(v);
                __nv_bfloat16 lo = __float2bfloat16(v - __bfloat162float(hi));
                g_xcat[(size_t)r * 3072 + c]        = hi;
                g_xcat[(size_t)r * 3072 + 1024 + c] = lo;
                g_xcat[(size_t)r * 3072 + 2048 + c] = hi;
            }
        }
        return;
    }
    const float* W = (z == 0) ? Wq : (z == 1) ? Wk : (z == 2) ? Wv : Wp;
    __nv_bfloat16* Wt = (z == 0) ? g_Wqt : (z == 1) ? g_Wkt : (z == 2) ? g_Wvt : g_Wpt;
    int ldt = (z < 2) ? 1024 : 3072;
    int split = (z < 2) ? 0 : 1;

    int tx = threadIdx.x & 31, ty = threadIdx.x >> 5;
    int k0 = blockIdx.y * 32, n0 = blockIdx.x * 32;
#pragma unroll
    for (int i = 0; i < 4; i++)
        tile[ty + i * 8][tx] = W[(size_t)(k0 + ty + i * 8) * C + n0 + tx];
    __syncthreads();
#pragma unroll
    for (int i = 0; i < 4; i++) {
        int n = n0 + ty + i * 8;
        int k = k0 + tx;
        float v = tile[tx][ty + i * 8];
        __nv_bfloat16 hi = __float2bfloat16(v);
        if (!split) {
            Wt[(size_t)n * ldt + k] = hi;
        } else {
            Wt[(size_t)n * ldt + k]        = hi;
            Wt[(size_t)n * ldt + 1024 + k] = hi;
            Wt[(size_t)n * ldt + 2048 + k] = __float2bfloat16(v - __bfloat162float(hi));
        }
    }
}

// ---- shared HMMA GEMM body (epi: 0 fp32, 1 bf16, 2 hi/lo bf16) ----
#define GSM_BYTES 65536

__device__ __forceinline__ void gemm_body(
    const __nv_bfloat16* __restrict__ A, int lda,
    const __nv_bfloat16* __restrict__ Bt, int ldb,
    float* __restrict__ Cf, __nv_bfloat16* __restrict__ Cb,
    __nv_bfloat16* __restrict__ Cb2, int ldc, int Kext, int epi, char* smem)
{
    const int tid = threadIdx.x;
    const int wid = tid >> 5;
    const int lane = tid & 31;
    const int bm = blockIdx.y * 128;
    const int bn = blockIdx.x * 128;
    const int mw = wid >> 1;
    const int nw = wid & 1;

    uint32_t sA[2], sB[2];
    sA[0] = smem_u32(smem);
    sB[0] = sA[0] + 16384;
    sA[1] = sA[0] + 32768;
    sB[1] = sA[0] + 49152;

    auto load_chunk = [&](int kc, int b) {
        const int k0 = kc << 6;
#pragma unroll
        for (int i = 0; i < 4; i++) {
            int idx = tid + i * 256;
            int row = idx >> 3;
            int g   = idx & 7;
            uint32_t so = SMEM_SWIZZLE_128B((uint32_t)(row * 128 + g * 16));
            cp_async16(sA[b] + so, A  + (size_t)(bm + row) * lda + k0 + g * 8);
            cp_async16(sB[b] + so, Bt + (size_t)(bn + row) * ldb + k0 + g * 8);
        }
        asm volatile("cp.async.commit_group;" ::: "memory");
    };

    float acc[2][8][4];
#pragma unroll
    for (int mf = 0; mf < 2; mf++)
#pragma unroll
        for (int nf = 0; nf < 8; nf++)
#pragma unroll
            for (int j = 0; j < 4; j++) acc[mf][nf][j] = 0.0f;

    const int NC = Kext >> 6;
    load_chunk(0, 0);

    for (int c = 0; c < NC; c++) {
        const int b = c & 1;
        if (c + 1 < NC) {
            load_chunk(c + 1, 1 - b);
            asm volatile("cp.async.wait_group 1;" ::: "memory");
        } else {
            asm volatile("cp.async.wait_group 0;" ::: "memory");
        }
        __syncthreads();

#pragma unroll
        for (int ks = 0; ks < 4; ks++) {
            uint32_t afrag[2][4];
#pragma unroll
            for (int mf = 0; mf < 2; mf++) {
                int row  = mw * 32 + mf * 16 + (lane & 15);
                int koff = ks * 32 + (lane >> 4) * 16;
                ldmatrix_x4(afrag[mf], sA[b] + SMEM_SWIZZLE_128B((uint32_t)(row * 128 + koff)));
            }
#pragma unroll
            for (int nfp = 0; nfp < 4; nfp++) {
                uint32_t bf[4];
                int nrow = nw * 64 + (2 * nfp + (lane >> 4)) * 8 + (lane & 7);
                int koff = ks * 32 + ((lane >> 3) & 1) * 16;
                ldmatrix_x4(bf, sB[b] + SMEM_SWIZZLE_128B((uint32_t)(nrow * 128 + koff)));
#pragma unroll
                for (int mf = 0; mf < 2; mf++) {
                    mma_bf16(acc[mf][2 * nfp],     afrag[mf], &bf[0]);
                    mma_bf16(acc[mf][2 * nfp + 1], afrag[mf], &bf[2]);
                }
            }
        }
        __syncthreads();
    }

    const int group = lane >> 2;
    const int tig   = lane & 3;
#pragma unroll
    for (int mf = 0; mf < 2; mf++) {
        int r0 = bm + mw * 32 + mf * 16 + group;
#pragma unroll
        for (int nf = 0; nf < 8; nf++) {
            int cc = bn + nw * 64 + nf * 8 + tig * 2;
            if (epi == 0) {
                *(float2*)&Cf[(size_t)r0 * ldc + cc]       = make_float2(acc[mf][nf][0], acc[mf][nf][1]);
                *(float2*)&Cf[(size_t)(r0 + 8) * ldc + cc] = make_float2(acc[mf][nf][2], acc[mf][nf][3]);
            } else if (epi == 1) {
                *(uint32_t*)(Cb + (size_t)r0 * ldc + cc)       = pack_bf16(acc[mf][nf][0], acc[mf][nf][1]);
                *(uint32_t*)(Cb + (size_t)(r0 + 8) * ldc + cc) = pack_bf16(acc[mf][nf][2], acc[mf][nf][3]);
            } else {
                uint32_t h0 = pack_bf16(acc[mf][nf][0], acc[mf][nf][1]);
                uint32_t h1 = pack_bf16(acc[mf][nf][2], acc[mf][nf][3]);
                *(uint32_t*)(Cb + (size_t)r0 * ldc + cc)       = h0;
                *(uint32_t*)(Cb + (size_t)(r0 + 8) * ldc + cc) = h1;
                *(uint32_t*)(Cb2 + (size_t)r0 * ldc + cc) =
                    pack_bf16(acc[mf][nf][0] - __uint_as_float(h0 << 16),
                              acc[mf][nf][1] - __uint_as_float(h0 & 0xFFFF0000u));
                *(uint32_t*)(Cb2 + (size_t)(r0 + 8) * ldc + cc) =
                    pack_bf16(acc[mf][nf][2] - __uint_as_float(h1 << 16),
                              acc[mf][nf][3] - __uint_as_float(h1 & 0xFFFF0000u));
            }
        }
    }
}

__global__ __launch_bounds__(256) void gemm_qkv_kernel()
{
    if (g_need == 0) return;
    extern __shared__ char smem[];
    int z = blockIdx.z;
    if (z == 0)
        gemm_body(g_xcat, 3072, g_Wqt, 1024, nullptr, g_Qraw, nullptr, C, 1024, 1, smem);
    else if (z == 1)
        gemm_body(g_xcat, 3072, g_Wkt, 1024, nullptr, g_Kraw, nullptr, C, 1024, 1, smem);
    else
        gemm_body(g_xcat, 3072, g_Wvt, 3072, nullptr, g_Vhi, g_Vlo, C, 3072, 2, smem);
}

__global__ __launch_bounds__(256) void gemm_fin_kernel(float* __restrict__ out)
{
    if (g_need == 0) return;
    extern __shared__ char smem[];
    gemm_body(g_ycat, 3072, g_Wpt, 3072, out, nullptr, nullptr, C, 3072, 0, smem);
}

// ---------------- RoPE + RMS-norm (gated) ----------------
__global__ void rope_rms_kernel(const float* __restrict__ cosT, const float* __restrict__ sinT)
{
    if (g_need == 0) return;
    int w    = (blockIdx.x * blockDim.x + threadIdx.x) >> 5;
    int lane = threadIdx.x & 31;
    int tensor = (w >= T * NH) ? 1 : 0;
    int rem    = tensor ? (w - T * NH) : w;
    int t = rem >> 4;
    int h = rem & 15;
    const __nv_bfloat16* p = (tensor ? g_Kraw : g_Qraw) + (size_t)t * C + h * HD;
    __nv_bfloat16* ob = (tensor ? g_Kb : g_Qb) + (size_t)t * C + h * HD;
    float sc = tensor ? 1.0f : 0.125f;

    float c  = cosT[t * 32 + lane];
    float s  = sinT[t * 32 + lane];
    float x1 = __bfloat162float(p[lane]);
    float x2 = __bfloat162float(p[lane + 32]);
    float o1 = x1 * c - x2 * s;
    float o2 = x1 * s + x2 * c;
    float ss = o1 * o1 + o2 * o2;
#pragma unroll
    for (int off = 16; off; off >>= 1) ss += __shfl_xor_sync(0xffffffffu, ss, off);
    float r = rsqrtf(ss * (1.0f / 64.0f) + EPSV) * sc;
    ob[lane]      = __float2bfloat16(o1 * r);
    ob[lane + 32] = __float2bfloat16(o2 * r);
}

// ---------------- flash attention on HMMA (gated) ----------------
#define ATT_SMEM 114688

__global__ __launch_bounds__(256) void attn_mma_kernel()
{
    if (g_need == 0) return;
    extern __shared__ char smc[];
    const uint32_t sQ = smem_u32(smc);
    const uint32_t sK[2]  = {sQ + 16384, sQ + 65536};
    const uint32_t sVh[2] = {sQ + 32768, sQ + 81920};
    const uint32_t sVl[2] = {sQ + 49152, sQ + 98304};

    const int tid = threadIdx.x, wid = tid >> 5, lane = tid & 31;
    const int h = blockIdx.y, q0 = blockIdx.x * 128;
    const int group = lane >> 2, tig = lane & 3;

    const __nv_bfloat16* Qg  = g_Qb  + (size_t)q0 * C + h * HD;
    const __nv_bfloat16* Kg  = g_Kb  + h * HD;
    const __nv_bfloat16* Vhg = g_Vhi + h * HD;
    const __nv_bfloat16* Vlg = g_Vlo + h * HD;

#pragma unroll
    for (int i = 0; i < 4; i++) {
        int idx = tid + i * 256;
        int row = idx >> 3, g = idx & 7;
        cp_async16(sQ + SMEM_SWIZZLE_128B((uint32_t)(row * 128 + g * 16)),
                   Qg + (size_t)row * C + g * 8);
    }
    auto loadKV = [&](int kt, int b) {
#pragma unroll
        for (int i = 0; i < 4; i++) {
            int idx = tid + i * 256;
            int row = idx >> 3, g = idx & 7;
            uint32_t so = SMEM_SWIZZLE_128B((uint32_t)(row * 128 + g * 16));
            size_t go = (size_t)(kt * 128 + row) * C + g * 8;
            cp_async16(sK[b]  + so, Kg  + go);
            cp_async16(sVh[b] + so, Vhg + go);
            cp_async16(sVl[b] + so, Vlg + go);
        }
        asm volatile("cp.async.commit_group;" ::: "memory");
    };
    loadKV(0, 0);

    float accs[16][4];
    float acco[8][4];
    float m0 = -3.0e38f, m1 = -3.0e38f, l0 = 0.0f, l1 = 0.0f;
#pragma unroll
    for (int nf = 0; nf < 8; nf++)
#pragma unroll
        for (int j = 0; j < 4; j++) acco[nf][j] = 0.0f;

    const int q_lo = q0 + wid * 16 + group;
    const int q_hi = q_lo + 8;

    for (int kt = 0; kt < 16; kt++) {
        const int b = kt & 1;
        if (kt + 1 < 16) {
            loadKV(kt + 1, 1 - b);
            asm volatile("cp.async.wait_group 1;" ::: "memory");
        } else {
            asm volatile("cp.async.wait_group 0;" ::: "memory");
        }
        __syncthreads();

#pragma unroll
        for (int nf = 0; nf < 16; nf++)
#pragma unroll
            for (int j = 0; j < 4; j++) accs[nf][j] = 0.0f;

#pragma unroll
        for (int ks = 0; ks < 4; ks++) {
            uint32_t af[4];
            {
                int row  = wid * 16 + (lane & 15);
                int koff = ks * 32 + (lane >> 4) * 16;
                ldmatrix_x4(af, sQ + SMEM_SWIZZLE_128B((uint32_t)(row * 128 + koff)));
            }
#pragma unroll
            for (int nfp = 0; nfp < 8; nfp++) {
                uint32_t bf[4];
                int nrow = (2 * nfp + (lane >> 4)) * 8 + (lane & 7);
                int koff = ks * 32 + ((lane >> 3) & 1) * 16;
                ldmatrix_x4(bf, sK[b] + SMEM_SWIZZLE_128B((uint32_t)(nrow * 128 + koff)));
                mma_bf16(accs[2 * nfp],     af, &bf[0]);
                mma_bf16(accs[2 * nfp + 1], af, &bf[2]);
            }
        }

        uint4 mk0 = *(const uint4*)(g_mask32 + (size_t)q_lo * 64 + kt * 4);
        uint4 mk1 = *(const uint4*)(g_mask32 + (size_t)q_hi * 64 + kt * 4);
        const unsigned* w0 = (const unsigned*)&mk0;
        const unsigned* w1 = (const unsigned*)&mk1;
        float mx0 = -3.0e38f, mx1 = -3.0e38f;
#pragma unroll
        for (int nf = 0; nf < 16; nf++) {
            int j = nf * 8 + tig * 2;
            unsigned b0 = w0[j >> 5] >> (j & 31);
            unsigned b1 = w1[j >> 5] >> (j & 31);
            accs[nf][0] = (b0 & 1) ? accs[nf][0] : NEGV;
            accs[nf][1] = (b0 & 2) ? accs[nf][1] : NEGV;
            accs[nf][2] = (b1 & 1) ? accs[nf][2] : NEGV;
            accs[nf][3] = (b1 & 2) ? accs[nf][3] : NEGV;
            mx0 = fmaxf(mx0, fmaxf(accs[nf][0], accs[nf][1]));
            mx1 = fmaxf(mx1, fmaxf(accs[nf][2], accs[nf][3]));
        }
        mx0 = fmaxf(mx0, __shfl_xor_sync(0xffffffffu, mx0, 1));
        mx0 = fmaxf(mx0, __shfl_xor_sync(0xffffffffu, mx0, 2));
        mx1 = fmaxf(mx1, __shfl_xor_sync(0xffffffffu, mx1, 1));
        mx1 = fmaxf(mx1, __shfl_xor_sync(0xffffffffu, mx1, 2));

        float mn0 = fmaxf(m0, mx0), mn1 = fmaxf(m1, mx1);
        float al0 = fast_exp(m0 - mn0), al1 = fast_exp(m1 - mn1);
        m0 = mn0; m1 = mn1;

        float s0 = 0.0f, s1 = 0.0f;
#pragma unroll
        for (int nf = 0; nf < 16; nf++) {
            accs[nf][0] = fast_exp(accs[nf][0] - mn0);
            accs[nf][1] = fast_exp(accs[nf][1] - mn0);
            accs[nf][2] = fast_exp(accs[nf][2] - mn1);
            accs[nf][3] = fast_exp(accs[nf][3] - mn1);
            s0 += accs[nf][0] + accs[nf][1];
            s1 += accs[nf][2] + accs[nf][3];
        }
        s0 += __shfl_xor_sync(0xffffffffu, s0, 1);
        s0 += __shfl_xor_sync(0xffffffffu, s0, 2);
        s1 += __shfl_xor_sync(0xffffffffu, s1, 1);
        s1 += __shfl_xor_sync(0xffffffffu, s1, 2);
        l0 = l0 * al0 + s0;
        l1 = l1 * al1 + s1;

#pragma unroll
        for (int nf = 0; nf < 8; nf++) {
            acco[nf][0] *= al0; acco[nf][1] *= al0;
            acco[nf][2] *= al1; acco[nf][3] *= al1;
        }

#pragma unroll
        for (int kb = 0; kb < 8; kb++) {
            uint32_t ah[4];
            float* s0p = accs[2 * kb];
            float* s1p = accs[2 * kb + 1];
            ah[0] = pack_bf16(s0p[0], s0p[1]);
            ah[1] = pack_bf16(s0p[2], s0p[3]);
            ah[2] = pack_bf16(s1p[0], s1p[1]);
            ah[3] = pack_bf16(s1p[2], s1p[3]);

            int vrow = kb * 16 + (lane & 15);
#pragma unroll
            for (int nfo = 0; nfo < 8; nfo++) {
                uint32_t so = SMEM_SWIZZLE_128B((uint32_t)(vrow * 128 + nfo * 16));
                uint32_t bh[2], bl[2];
                ldmatrix_x2_trans(bh, sVh[b] + so);
                ldmatrix_x2_trans(bl, sVl[b] + so);
                mma_bf16(acco[nfo], ah, bh);
                mma_bf16(acco[nfo], ah, bl);
            }
        }
        __syncthreads();
    }

    float invl[2] = {1.0f / l0, 1.0f / l1};
    int qrow[2] = {q_lo, q_hi};
#pragma unroll
    for (int rr = 0; rr < 2; rr++) {
        __nv_bfloat16* yr = g_ycat + (size_t)qrow[rr] * 3072 + h * HD;
#pragma unroll
        for (int nfo = 0; nfo < 8; nfo++) {
            float o0 = acco[nfo][2 * rr + 0] * invl[rr];
            float o1 = acco[nfo][2 * rr + 1] * invl[rr];
            uint32_t hi = pack_bf16(o0, o1);
            uint32_t lo = pack_bf16(o0 - __uint_as_float(hi << 16),
                                    o1 - __uint_as_float(hi & 0xFFFF0000u));
            int col = nfo * 8 + tig * 2;
            *(uint32_t*)(yr + col)        = hi;
            *(uint32_t*)(yr + 1024 + col) = lo;
            *(uint32_t*)(yr + 2048 + col) = hi;
        }
    }
}

// ---------------- launch ----------------
extern "C" void kernel_launch(void* const* d_in, const int* in_sizes, int n_in,
                              void* d_out, int out_size)
{
    const float* x    = (const float*)d_in[0];
    const float* cosT = (const float*)d_in[1];
    const float* sinT = (const float*)d_in[2];
    const float* Wq   = (const float*)d_in[3];
    const float* Wk   = (const float*)d_in[4];
    const float* Wv   = (const float*)d_in[5];
    const float* Wp   = (const float*)d_in[6];
    const float* Wdq  = (const float*)d_in[7];
    const float* Wdk  = (const float*)d_in[8];
    float* out = (float*)d_out;

    cudaFuncSetAttribute(gemm_qkv_kernel, cudaFuncAttributeMaxDynamicSharedMemorySize, GSM_BYTES);
    cudaFuncSetAttribute(gemm_fin_kernel, cudaFuncAttributeMaxDynamicSharedMemorySize, GSM_BYTES);
    cudaFuncSetAttribute(attn_mma_kernel, cudaFuncAttributeMaxDynamicSharedMemorySize, ATT_SMEM);

    // ---- always: fused mask + generic-path algebra + broadcast (one launch) ----
    fused_light_kernel<<<GRID_F, 256>>>(x, Wdq, Wdk, Wv, Wp, out);

    // ---- gated heavy path (early-exits when g_need == 0) ----
    prep_kernel<<<dim3(32, 32, 5), 256>>>(x, Wq, Wk, Wv, Wp);
    gemm_qkv_kernel<<<dim3(C / 128, T / 128, 3), 256, GSM_BYTES>>>();
    rope_rms_kernel<<<(2 * T * NH * 32) / 256, 256>>>(cosT, sinT);
    attn_mma_kernel<<<dim3(T / 128, NH), 256, ATT_SMEM>>>();
    gemm_fin_kernel<<<dim3(C / 128, T / 128), 256, GSM_BYTES>>>(out);
}